// round 12
// baseline (speedup 1.0000x reference)
#include <cuda_runtime.h>
#include <cstdint>

// Problem constants
#define B_   32
#define C_   256
#define H_   58
#define W_   58
#define OC_  256
#define KH_  3
#define KW_  3
#define HO_  56
#define WO_  56
#define HW_  (H_*W_)            // 3364
#define NWORDS 8                // 256 channels / 32 bits
#define CN_  2304               // C*KH*KW
#define NINPUT 861184.0f        // C*H*W (alpha normalizer)

// Scratch (device globals; no allocations allowed)
__device__ unsigned g_xpack[B_ * HW_ * NWORDS];        // [b][y][x][w]  3.44 MB
__device__ unsigned g_wpack[OC_ * KH_ * KW_ * NWORDS]; // [o][k][w]     73.7 KB
__device__ float    g_alpha[OC_];

// Forced single-LOP3 3-input ops
template <int LUT>
__device__ __forceinline__ unsigned lop3(unsigned a, unsigned b, unsigned c) {
    unsigned r;
    asm("lop3.b32 %0, %1, %2, %3, %4;" : "=r"(r) : "r"(a), "r"(b), "r"(c), "n"(LUT));
    return r;
}
#define XOR3(a,b,c)  lop3<0x96>(a,b,c)                 // a^b^c
#define MAJ3(a,b,c)  lop3<0xE8>(a,b,c)                 // majority
#define MAJU(x,y,u)  lop3<0xD4>(x,y,u)                 // (x&y)|((x^y)&~u)

// ---------------------------------------------------------------------------
// Fused pack kernel (unchanged from R10).
// ---------------------------------------------------------------------------
#define XBLOCKS (B_ * NWORDS * 7)   // 1792

__global__ void __launch_bounds__(256) pack_kernel(const float* __restrict__ x,
                                                   const float* __restrict__ wgt) {
    int blk = blockIdx.x;
    if (blk < XBLOCKS) {
        int b    = blk / 56;
        int rem  = blk % 56;
        int w    = rem / 7;
        int pblk = rem % 7;
        int pos0 = pblk * 512 + threadIdx.x;

        const float* xp = x + ((size_t)(b * C_ + w * 32) * HW_);
        float v0[32], v1[32];
        bool ok0 = pos0 < HW_;
        bool ok1 = pos0 + 256 < HW_;
#pragma unroll
        for (int c = 0; c < 32; c++) {
            size_t off = (size_t)c * HW_;
            v0[c] = ok0 ? __ldg(xp + off + pos0)       : 0.f;
            v1[c] = ok1 ? __ldg(xp + off + pos0 + 256) : 0.f;
        }
        unsigned bits0 = 0, bits1 = 0;
#pragma unroll
        for (int c = 0; c < 32; c++) {
            bits0 |= (v0[c] > 0.5f ? 1u : 0u) << c;
            bits1 |= (v1[c] > 0.5f ? 1u : 0u) << c;
        }
        if (ok0) g_xpack[((size_t)b * HW_ + pos0) * NWORDS + w] = bits0;
        if (ok1) g_xpack[((size_t)b * HW_ + pos0 + 256) * NWORDS + w] = bits1;
    } else {
        int o = blk - XBLOCKS;
        int c = threadIdx.x;
        int lane = c & 31;
        int wrp  = c >> 5;

        const float* wp = wgt + (size_t)(o * C_ + c) * (KH_ * KW_);
        float asum = 0.f;
#pragma unroll
        for (int k = 0; k < KH_ * KW_; k++) {
            float v = wp[k];
            asum += fabsf(v);
            unsigned word = __ballot_sync(0xffffffffu, v >= 0.f);
            if (lane == 0) g_wpack[(o * 9 + k) * NWORDS + wrp] = word;
        }

        __shared__ float red[256];
        red[c] = asum;
        __syncthreads();
#pragma unroll
        for (int s = 128; s > 0; s >>= 1) {
            if (c < s) red[c] += red[c + s];
            __syncthreads();
        }
        if (c == 0) g_alpha[o] = red[0] / NINPUT;
    }
}

// ---------------------------------------------------------------------------
// Conv: R10 math (two-level CSA, X=2, 96+32 LOP3 + 32 POPC per output) with
// ALL per-thread weights in shared memory (conflict-free uint4 layout) to cut
// registers below 128 -> 4 CTAs/SM = 16 warps (vs R10's 3 CTAs @ 168 regs).
// Weight chunks reloaded per x0 iteration: 9 LDS.128/output (cheap vs alu).
// grid = (B_*HO_, 2), block = 128 (thread = output channel within half).
// ---------------------------------------------------------------------------
__global__ void __launch_bounds__(128, 4)
xnor_conv_kernel(float* __restrict__ out) {
    int by = blockIdx.x;
    int b  = by / HO_;
    int y  = by % HO_;
    int t  = threadIdx.x;
    int o  = blockIdx.y * 128 + t;

    __shared__ __align__(16) unsigned sx[3 * W_  * NWORDS];  // 5568 B
    __shared__ __align__(16) unsigned s3[3 * WO_ * NWORDS];  // 5376 B
    // weights: [chunk = (kh*2+half)*3 + cls][o_local], cls: 0=w0,1=w1,2=wx3
    __shared__ uint4 w4[18][128];                            // 36864 B

    // load 3 packed rows
    const int ROW4 = W_ * NWORDS / 4; // 116 uint4 per row
    for (int i = t; i < 3 * ROW4; i += 128) {
        int kh = i / ROW4;
        int r  = i - kh * ROW4;
        const uint4* src = (const uint4*)(g_xpack + ((size_t)(b * H_ + y + kh) * W_) * NWORDS);
        ((uint4*)sx)[kh * ROW4 + r] = src[r];
    }

    // fill weight smem: per (kh, half): w0, w1, wx3 as uint4 over j
    {
        const uint4* wp4 = (const uint4*)(g_wpack + (size_t)o * 72);
#pragma unroll
        for (int kh = 0; kh < 3; kh++) {
#pragma unroll
            for (int half = 0; half < 2; half++) {
                uint4 a = wp4[(kh * 3 + 0) * 2 + half];
                uint4 bq = wp4[(kh * 3 + 1) * 2 + half];
                uint4 c = wp4[(kh * 3 + 2) * 2 + half];
                int ch = (kh * 2 + half) * 3;
                w4[ch + 0][t] = a;
                w4[ch + 1][t] = bq;
                uint4 xx;
                xx.x = a.x ^ bq.x ^ c.x;
                xx.y = a.y ^ bq.y ^ c.y;
                xx.z = a.z ^ bq.z ^ c.z;
                xx.w = a.w ^ bq.w ^ c.w;
                w4[ch + 2][t] = xx;
            }
        }
    }
    float a = g_alpha[o];
    float base = a * (float)CN_;     // out = base + na * P
    float na   = -2.0f * a;
    __syncthreads();

    // s3[kh][c][w] = sx[kh][c] ^ sx[kh][c+1] ^ sx[kh][c+2]
    for (int i = t; i < 3 * WO_ * NWORDS; i += 128) {
        int kh = i / (WO_ * NWORDS);
        int r  = i - kh * (WO_ * NWORDS);
        int bidx = kh * (W_ * NWORDS) + r;
        s3[i] = XOR3(sx[bidx], sx[bidx + NWORDS], sx[bidx + 2 * NWORDS]);
    }
    __syncthreads();

    float* outp = out + ((size_t)(b * OC_ + o) * HO_ + y) * WO_;

#pragma unroll 2
    for (int x0 = 0; x0 < WO_; x0 += 2) {
        int Su0 = 0, Cu0 = 0, Sv0 = 0, Cv0 = 0;
        int Su1 = 0, Cu1 = 0, Sv1 = 0, Cv1 = 0;
#pragma unroll
        for (int half = 0; half < 2; half++) {
            unsigned u[3][2][4], v[3][2][4];     // [kh][xi][j]
#pragma unroll
            for (int kh = 0; kh < 3; kh++) {
                const unsigned* rp = &sx[(kh * W_ + x0) * NWORDS + half * 4];
                uint4 q0 = *(const uint4*)(rp);
                uint4 q1 = *(const uint4*)(rp + NWORDS);
                uint4 q2 = *(const uint4*)(rp + 2 * NWORDS);
                const unsigned* rs = &s3[(kh * WO_ + x0) * NWORDS + half * 4];
                uint4 t0 = *(const uint4*)(rs);
                uint4 t1 = *(const uint4*)(rs + NWORDS);

                int ch = (kh * 2 + half) * 3;
                uint4 W0 = w4[ch + 0][t];
                uint4 W1 = w4[ch + 1][t];
                uint4 WX = w4[ch + 2][t];

                unsigned p0[4] = {q0.x, q0.y, q0.z, q0.w};
                unsigned p1[4] = {q1.x, q1.y, q1.z, q1.w};
                unsigned p2[4] = {q2.x, q2.y, q2.z, q2.w};
                unsigned s0[4] = {t0.x, t0.y, t0.z, t0.w};
                unsigned s1[4] = {t1.x, t1.y, t1.z, t1.w};
                unsigned Wa[4] = {W0.x, W0.y, W0.z, W0.w};
                unsigned Wb[4] = {W1.x, W1.y, W1.z, W1.w};
                unsigned Wx[4] = {WX.x, WX.y, WX.z, WX.w};
#pragma unroll
                for (int j = 0; j < 4; j++) {
                    unsigned u0 = s0[j] ^ Wx[j];
                    unsigned u1 = s1[j] ^ Wx[j];
                    u[kh][0][j] = u0;
                    u[kh][1][j] = u1;
                    v[kh][0][j] = MAJU(p0[j] ^ Wa[j], p1[j] ^ Wb[j], u0);
                    v[kh][1][j] = MAJU(p1[j] ^ Wa[j], p2[j] ^ Wb[j], u1);
                }
            }
#pragma unroll
            for (int j = 0; j < 4; j++) {
                Su0 += __popc(XOR3(u[0][0][j], u[1][0][j], u[2][0][j]));
                Cu0 += __popc(MAJ3(u[0][0][j], u[1][0][j], u[2][0][j]));
                Sv0 += __popc(XOR3(v[0][0][j], v[1][0][j], v[2][0][j]));
                Cv0 += __popc(MAJ3(v[0][0][j], v[1][0][j], v[2][0][j]));
                Su1 += __popc(XOR3(u[0][1][j], u[1][1][j], u[2][1][j]));
                Cu1 += __popc(MAJ3(u[0][1][j], u[1][1][j], u[2][1][j]));
                Sv1 += __popc(XOR3(v[0][1][j], v[1][1][j], v[2][1][j]));
                Cv1 += __popc(MAJ3(v[0][1][j], v[1][1][j], v[2][1][j]));
            }
        }
        int P0 = Su0 + ((Cu0 + Sv0) << 1) + (Cv0 << 2);
        int P1 = Su1 + ((Cu1 + Sv1) << 1) + (Cv1 << 2);
        float2 r;
        r.x = fmaf(na, (float)P0, base);
        r.y = fmaf(na, (float)P1, base);
        *(float2*)(outp + x0) = r;
    }
}

// ---------------------------------------------------------------------------
extern "C" void kernel_launch(void* const* d_in, const int* in_sizes, int n_in,
                              void* d_out, int out_size) {
    const float* x   = (const float*)d_in[0];
    const float* wgt = (const float*)d_in[1];
    float* out = (float*)d_out;

    pack_kernel<<<XBLOCKS + OC_, 256>>>(x, wgt);
    dim3 g3(B_ * HO_, 2);
    xnor_conv_kernel<<<g3, 128>>>(out);
}

// round 13
// speedup vs baseline: 1.5568x; 1.5568x over previous
#include <cuda_runtime.h>
#include <cstdint>

// Problem constants
#define B_   32
#define C_   256
#define H_   58
#define W_   58
#define OC_  256
#define HO_  56
#define WO_  56
#define HW_  (H_*W_)            // 3364
#define NWORDS 8                // 256 channels / 32 bits
#define CN_  2304               // C*KH*KW
#define NINPUT 861184.0f        // C*H*W (alpha normalizer)

// Scratch (device globals; no allocations allowed)
__device__ unsigned g_xpack[B_ * HW_ * NWORDS];        // [b][y][x][w]  3.44 MB
// CSA-form weights: per o, 18 uint4 chunks: chunk=(kh*2+half)*3+cls,
// cls 0 = W0 (kw0), 1 = W1 (kw1), 2 = WX = W0^W1^W2. 73.7 KB, L2-resident.
__device__ uint4    g_wcsa[OC_ * 18];
__device__ float    g_alpha[OC_];

// Forced single-LOP3 3-input ops
template <int LUT>
__device__ __forceinline__ unsigned lop3(unsigned a, unsigned b, unsigned c) {
    unsigned r;
    asm("lop3.b32 %0, %1, %2, %3, %4;" : "=r"(r) : "r"(a), "r"(b), "r"(c), "n"(LUT));
    return r;
}
#define XOR3(a,b,c)  lop3<0x96>(a,b,c)                 // a^b^c
#define MAJ3(a,b,c)  lop3<0xE8>(a,b,c)                 // majority
#define MAJU(x,y,u)  lop3<0xD4>(x,y,u)                 // (x&y)|((x^y)&~u)

// ---------------------------------------------------------------------------
// Fused pack kernel. blocks [0,1792): activations; [1792,2048): weights.
// ---------------------------------------------------------------------------
#define XBLOCKS (B_ * NWORDS * 7)   // 1792

__global__ void __launch_bounds__(256) pack_kernel(const float* __restrict__ x,
                                                   const float* __restrict__ wgt) {
    int blk = blockIdx.x;
    if (blk < XBLOCKS) {
        int b    = blk / 56;
        int rem  = blk % 56;
        int w    = rem / 7;
        int pblk = rem % 7;
        int pos0 = pblk * 512 + threadIdx.x;

        const float* xp = x + ((size_t)(b * C_ + w * 32) * HW_);
        float v0[32], v1[32];
        bool ok0 = pos0 < HW_;
        bool ok1 = pos0 + 256 < HW_;
#pragma unroll
        for (int c = 0; c < 32; c++) {
            size_t off = (size_t)c * HW_;
            v0[c] = ok0 ? __ldg(xp + off + pos0)       : 0.f;
            v1[c] = ok1 ? __ldg(xp + off + pos0 + 256) : 0.f;
        }
        unsigned bits0 = 0, bits1 = 0;
#pragma unroll
        for (int c = 0; c < 32; c++) {
            bits0 |= (v0[c] > 0.5f ? 1u : 0u) << c;
            bits1 |= (v1[c] > 0.5f ? 1u : 0u) << c;
        }
        if (ok0) g_xpack[((size_t)b * HW_ + pos0) * NWORDS + w] = bits0;
        if (ok1) g_xpack[((size_t)b * HW_ + pos0 + 256) * NWORDS + w] = bits1;
    } else {
        // weight packing: ballot bits -> smem, then build g_wcsa + alpha
        int o = blk - XBLOCKS;
        int c = threadIdx.x;
        int lane = c & 31;
        int wrp  = c >> 5;

        __shared__ unsigned sw[72];        // [tap 0..8][word 0..7]
        __shared__ float red[256];

        const float* wp = wgt + (size_t)(o * C_ + c) * 9;
        float asum = 0.f;
#pragma unroll
        for (int k = 0; k < 9; k++) {
            float v = wp[k];
            asum += fabsf(v);
            unsigned word = __ballot_sync(0xffffffffu, v >= 0.f);
            if (lane == 0) sw[k * 8 + wrp] = word;
        }
        red[c] = asum;
        __syncthreads();

        if (c < 72) {
            int chunk = c >> 2, wc = c & 3;
            int kh = chunk / 6, r = chunk % 6;
            int half = r / 3, cls = r % 3;
            int widx = half * 4 + wc;                 // word 0..7
            unsigned val;
            if (cls < 2) val = sw[(kh * 3 + cls) * 8 + widx];
            else         val = sw[(kh * 3 + 0) * 8 + widx]
                             ^ sw[(kh * 3 + 1) * 8 + widx]
                             ^ sw[(kh * 3 + 2) * 8 + widx];
            ((unsigned*)g_wcsa)[o * 72 + chunk * 4 + wc] = val;
        }
#pragma unroll
        for (int s = 128; s > 0; s >>= 1) {
            if (c < s) red[c] += red[c + s];
            __syncthreads();
        }
        if (c == 0) g_alpha[o] = red[0] / NINPUT;
    }
}

// ---------------------------------------------------------------------------
// Conv: thread = (row, x). Pixels + s3 column live in REGISTERS for the whole
// block; loop over output channels o; weights arrive as uniform (warp-
// broadcast) LDG.128 from g_wcsa. Same two-level CSA math as R10:
// per word: u = s3^WX; v = MAJU(pa^W0, pb^W1, u); level-2 XOR3/MAJ3 over kh;
// 4 POPC per word with weights (1,2,2,4).
// Block = 224 threads = 4 rows x 56 x (zero idle lanes).
// grid = (14*B_, 4): blockIdx.x -> (b, y-group of 4), blockIdx.y -> 64-o slice.
// ---------------------------------------------------------------------------
__global__ void __launch_bounds__(224, 2)
xnor_conv_kernel(float* __restrict__ out) {
    int bx = blockIdx.x;
    int b  = bx / 14;
    int y0 = (bx % 14) * 4;
    int t  = threadIdx.x;
    int ry = t / 56;
    int xx = t - ry * 56;
    int y  = y0 + ry;
    int o0 = blockIdx.y * 64;

    __shared__ __align__(16) unsigned srow[6 * W_ * NWORDS];  // 11136 B

    // stage 6 contiguous pixel rows (y0 .. y0+5)
    {
        const uint4* src = (const uint4*)(g_xpack + ((size_t)(b * H_ + y0) * W_) * NWORDS);
        const int N4 = 6 * W_ * NWORDS / 4;   // 696
        for (int i = t; i < N4; i += 224) ((uint4*)srow)[i] = src[i];
    }
    __syncthreads();

    // per-thread pixel registers: cols xx (pa), xx+1 (pb), s3 = xx^xx+1^xx+2
    unsigned pa[24], pb[24], s3r[24];          // [kh*8 + w]
#pragma unroll
    for (int kh = 0; kh < 3; kh++) {
        int rbase = ((ry + kh) * W_ + xx) * NWORDS;
        uint4 A0 = *(const uint4*)&srow[rbase];
        uint4 A1 = *(const uint4*)&srow[rbase + 4];
        uint4 B0 = *(const uint4*)&srow[rbase + 8];
        uint4 B1 = *(const uint4*)&srow[rbase + 12];
        uint4 C0 = *(const uint4*)&srow[rbase + 16];
        uint4 C1 = *(const uint4*)&srow[rbase + 20];
        pa[kh*8+0]=A0.x; pa[kh*8+1]=A0.y; pa[kh*8+2]=A0.z; pa[kh*8+3]=A0.w;
        pa[kh*8+4]=A1.x; pa[kh*8+5]=A1.y; pa[kh*8+6]=A1.z; pa[kh*8+7]=A1.w;
        pb[kh*8+0]=B0.x; pb[kh*8+1]=B0.y; pb[kh*8+2]=B0.z; pb[kh*8+3]=B0.w;
        pb[kh*8+4]=B1.x; pb[kh*8+5]=B1.y; pb[kh*8+6]=B1.z; pb[kh*8+7]=B1.w;
        s3r[kh*8+0]=XOR3(A0.x,B0.x,C0.x); s3r[kh*8+1]=XOR3(A0.y,B0.y,C0.y);
        s3r[kh*8+2]=XOR3(A0.z,B0.z,C0.z); s3r[kh*8+3]=XOR3(A0.w,B0.w,C0.w);
        s3r[kh*8+4]=XOR3(A1.x,B1.x,C1.x); s3r[kh*8+5]=XOR3(A1.y,B1.y,C1.y);
        s3r[kh*8+6]=XOR3(A1.z,B1.z,C1.z); s3r[kh*8+7]=XOR3(A1.w,B1.w,C1.w);
    }

    float* outp = out + (((size_t)b * OC_ + o0) * HO_ + y) * WO_ + xx;
    const uint4* __restrict__ wp = g_wcsa + (size_t)o0 * 18;

#pragma unroll 2
    for (int oi = 0; oi < 64; oi++) {
        int Su = 0, Cu = 0, Sv = 0, Cv = 0;
#pragma unroll
        for (int half = 0; half < 2; half++) {
            unsigned u[3][4], v[3][4];
#pragma unroll
            for (int kh = 0; kh < 3; kh++) {
                int ch = (kh * 2 + half) * 3;
                uint4 W0 = __ldg(wp + ch);
                uint4 W1 = __ldg(wp + ch + 1);
                uint4 WX = __ldg(wp + ch + 2);
                unsigned Wa[4] = {W0.x, W0.y, W0.z, W0.w};
                unsigned Wb[4] = {W1.x, W1.y, W1.z, W1.w};
                unsigned Wx[4] = {WX.x, WX.y, WX.z, WX.w};
#pragma unroll
                for (int j = 0; j < 4; j++) {
                    int idx = kh * 8 + half * 4 + j;
                    unsigned uu = s3r[idx] ^ Wx[j];
                    u[kh][j] = uu;
                    v[kh][j] = MAJU(pa[idx] ^ Wa[j], pb[idx] ^ Wb[j], uu);
                }
            }
#pragma unroll
            for (int j = 0; j < 4; j++) {
                Su += __popc(XOR3(u[0][j], u[1][j], u[2][j]));
                Cu += __popc(MAJ3(u[0][j], u[1][j], u[2][j]));
                Sv += __popc(XOR3(v[0][j], v[1][j], v[2][j]));
                Cv += __popc(MAJ3(v[0][j], v[1][j], v[2][j]));
            }
        }
        int P = Su + ((Cu + Sv) << 1) + (Cv << 2);
        float a = __ldg(&g_alpha[o0 + oi]);
        *outp = fmaf(-2.0f * a, (float)P, a * (float)CN_);
        outp += (size_t)HO_ * WO_;
        wp += 18;
    }
}

// ---------------------------------------------------------------------------
extern "C" void kernel_launch(void* const* d_in, const int* in_sizes, int n_in,
                              void* d_out, int out_size) {
    const float* x   = (const float*)d_in[0];
    const float* wgt = (const float*)d_in[1];
    float* out = (float*)d_out;

    pack_kernel<<<XBLOCKS + OC_, 256>>>(x, wgt);
    dim3 g3(14 * B_, 4);
    xnor_conv_kernel<<<g3, 224>>>(out);
}

// round 14
// speedup vs baseline: 1.5831x; 1.0169x over previous
#include <cuda_runtime.h>
#include <cstdint>

// Problem constants
#define B_   32
#define C_   256
#define H_   58
#define W_   58
#define OC_  256
#define HO_  56
#define WO_  56
#define HW_  (H_*W_)            // 3364
#define NWORDS 8                // 256 channels / 32 bits
#define CN_  2304               // C*KH*KW
#define NINPUT 861184.0f        // C*H*W (alpha normalizer)

// Scratch (device globals; no allocations allowed)
__device__ unsigned g_xpack[B_ * HW_ * NWORDS];        // [b][y][x][w]  3.44 MB
// CSA-form weights: per o, 18 uint4 chunks: chunk=(kh*2+half)*3+cls,
// cls 0 = W0 (kw0), 1 = W1 (kw1), 2 = WX = W0^W1^W2. 73.7 KB, L2-resident.
__device__ uint4    g_wcsa[OC_ * 18];
__device__ float    g_alpha[OC_];

// Forced single-LOP3 3-input ops
template <int LUT>
__device__ __forceinline__ unsigned lop3(unsigned a, unsigned b, unsigned c) {
    unsigned r;
    asm("lop3.b32 %0, %1, %2, %3, %4;" : "=r"(r) : "r"(a), "r"(b), "r"(c), "n"(LUT));
    return r;
}
#define XOR3(a,b,c)  lop3<0x96>(a,b,c)                 // a^b^c
#define MAJ3(a,b,c)  lop3<0xE8>(a,b,c)                 // majority
#define MAJU(x,y,u)  lop3<0xD4>(x,y,u)                 // (x&y)|((x^y)&~u)

// ---------------------------------------------------------------------------
// Fused pack kernel. blocks [0,1792): activations; [1792,2048): weights.
// ---------------------------------------------------------------------------
#define XBLOCKS (B_ * NWORDS * 7)   // 1792

__global__ void __launch_bounds__(256) pack_kernel(const float* __restrict__ x,
                                                   const float* __restrict__ wgt) {
    int blk = blockIdx.x;
    if (blk < XBLOCKS) {
        int b    = blk / 56;
        int rem  = blk % 56;
        int w    = rem / 7;
        int pblk = rem % 7;
        int pos0 = pblk * 512 + threadIdx.x;

        const float* xp = x + ((size_t)(b * C_ + w * 32) * HW_);
        float v0[32], v1[32];
        bool ok0 = pos0 < HW_;
        bool ok1 = pos0 + 256 < HW_;
#pragma unroll
        for (int c = 0; c < 32; c++) {
            size_t off = (size_t)c * HW_;
            v0[c] = ok0 ? __ldg(xp + off + pos0)       : 0.f;
            v1[c] = ok1 ? __ldg(xp + off + pos0 + 256) : 0.f;
        }
        unsigned bits0 = 0, bits1 = 0;
#pragma unroll
        for (int c = 0; c < 32; c++) {
            bits0 |= (v0[c] > 0.5f ? 1u : 0u) << c;
            bits1 |= (v1[c] > 0.5f ? 1u : 0u) << c;
        }
        if (ok0) g_xpack[((size_t)b * HW_ + pos0) * NWORDS + w] = bits0;
        if (ok1) g_xpack[((size_t)b * HW_ + pos0 + 256) * NWORDS + w] = bits1;
    } else {
        // weight packing: ballot bits -> smem, then build g_wcsa + alpha
        int o = blk - XBLOCKS;
        int c = threadIdx.x;
        int lane = c & 31;
        int wrp  = c >> 5;

        __shared__ unsigned sw[72];        // [tap 0..8][word 0..7]
        __shared__ float red[256];

        const float* wp = wgt + (size_t)(o * C_ + c) * 9;
        float asum = 0.f;
#pragma unroll
        for (int k = 0; k < 9; k++) {
            float v = wp[k];
            asum += fabsf(v);
            unsigned word = __ballot_sync(0xffffffffu, v >= 0.f);
            if (lane == 0) sw[k * 8 + wrp] = word;
        }
        red[c] = asum;
        __syncthreads();

        if (c < 72) {
            int chunk = c >> 2, wc = c & 3;
            int kh = chunk / 6, r = chunk % 6;
            int half = r / 3, cls = r % 3;
            int widx = half * 4 + wc;                 // word 0..7
            unsigned val;
            if (cls < 2) val = sw[(kh * 3 + cls) * 8 + widx];
            else         val = sw[(kh * 3 + 0) * 8 + widx]
                             ^ sw[(kh * 3 + 1) * 8 + widx]
                             ^ sw[(kh * 3 + 2) * 8 + widx];
            ((unsigned*)g_wcsa)[o * 72 + chunk * 4 + wc] = val;
        }
#pragma unroll
        for (int s = 128; s > 0; s >>= 1) {
            if (c < s) red[c] += red[c + s];
            __syncthreads();
        }
        if (c == 0) g_alpha[o] = red[0] / NINPUT;
    }
}

// ---------------------------------------------------------------------------
// Conv: thread-pair = (row, x); each thread of the pair owns 4 channel words
// (half). Pixels + s3 in registers (36 regs, spill-free); weights arrive as
// warp-broadcast LDG.128 from g_wcsa; per-output partial P combined with one
// __shfl_xor_sync (P additive over words).
// Two-level CSA: u = s3^WX; v = MAJU(pa^W0, pb^W1, u); XOR3/MAJ3 over kh;
// 4 POPC per word, weights (1,2,2,4).
// Block = 448 threads = 224 spatial x 2 halves; grid = (14*B_, 4 o-slices).
// ---------------------------------------------------------------------------
__global__ void __launch_bounds__(448, 1)
xnor_conv_kernel(float* __restrict__ out) {
    int bx = blockIdx.x;
    int b  = bx / 14;
    int y0 = (bx % 14) * 4;
    int t  = threadIdx.x;
    int half = t & 1;
    int s  = t >> 1;                 // 0..223
    int ry = s / 56;
    int xx = s - ry * 56;
    int y  = y0 + ry;
    int o0 = blockIdx.y * 64;

    __shared__ __align__(16) unsigned srow[6 * W_ * NWORDS];  // 11136 B

    // stage 6 contiguous pixel rows (y0 .. y0+5)
    {
        const uint4* src = (const uint4*)(g_xpack + ((size_t)(b * H_ + y0) * W_) * NWORDS);
        const int N4 = 6 * W_ * NWORDS / 4;   // 696
        for (int i = t; i < N4; i += 448) ((uint4*)srow)[i] = src[i];
    }
    __syncthreads();

    // per-thread pixel registers for this half: cols xx (pa), xx+1 (pb),
    // s3 = xx ^ xx+1 ^ xx+2;   layout [kh*4 + j]
    unsigned pa[12], pb[12], s3r[12];
#pragma unroll
    for (int kh = 0; kh < 3; kh++) {
        int rbase = ((ry + kh) * W_ + xx) * NWORDS + half * 4;
        uint4 A = *(const uint4*)&srow[rbase];
        uint4 Bq = *(const uint4*)&srow[rbase + 8];
        uint4 Cq = *(const uint4*)&srow[rbase + 16];
        pa[kh*4+0]=A.x;  pa[kh*4+1]=A.y;  pa[kh*4+2]=A.z;  pa[kh*4+3]=A.w;
        pb[kh*4+0]=Bq.x; pb[kh*4+1]=Bq.y; pb[kh*4+2]=Bq.z; pb[kh*4+3]=Bq.w;
        s3r[kh*4+0]=XOR3(A.x,Bq.x,Cq.x); s3r[kh*4+1]=XOR3(A.y,Bq.y,Cq.y);
        s3r[kh*4+2]=XOR3(A.z,Bq.z,Cq.z); s3r[kh*4+3]=XOR3(A.w,Bq.w,Cq.w);
    }

    float* outp = out + (((size_t)b * OC_ + o0) * HO_ + y) * WO_ + xx;
    // this thread's weight chunks: (kh*2+half)*3 + cls
    const uint4* __restrict__ wp = g_wcsa + (size_t)o0 * 18 + half * 3;

#pragma unroll 2
    for (int oi = 0; oi < 64; oi++) {
        unsigned u[3][4], v[3][4];
#pragma unroll
        for (int kh = 0; kh < 3; kh++) {
            uint4 W0 = __ldg(wp + kh * 6);
            uint4 W1 = __ldg(wp + kh * 6 + 1);
            uint4 WX = __ldg(wp + kh * 6 + 2);
            unsigned Wa[4] = {W0.x, W0.y, W0.z, W0.w};
            unsigned Wb[4] = {W1.x, W1.y, W1.z, W1.w};
            unsigned Wx[4] = {WX.x, WX.y, WX.z, WX.w};
#pragma unroll
            for (int j = 0; j < 4; j++) {
                int idx = kh * 4 + j;
                unsigned uu = s3r[idx] ^ Wx[j];
                u[kh][j] = uu;
                v[kh][j] = MAJU(pa[idx] ^ Wa[j], pb[idx] ^ Wb[j], uu);
            }
        }
        int Su = 0, Cu = 0, Sv = 0, Cv = 0;
#pragma unroll
        for (int j = 0; j < 4; j++) {
            Su += __popc(XOR3(u[0][j], u[1][j], u[2][j]));
            Cu += __popc(MAJ3(u[0][j], u[1][j], u[2][j]));
            Sv += __popc(XOR3(v[0][j], v[1][j], v[2][j]));
            Cv += __popc(MAJ3(v[0][j], v[1][j], v[2][j]));
        }
        int P = Su + ((Cu + Sv) << 1) + (Cv << 2);
        P += __shfl_xor_sync(0xffffffffu, P, 1);
        if (half == 0) {
            float a = __ldg(&g_alpha[o0 + oi]);
            *outp = fmaf(-2.0f * a, (float)P, a * (float)CN_);
        }
        outp += (size_t)HO_ * WO_;
        wp += 18;
    }
}

// ---------------------------------------------------------------------------
extern "C" void kernel_launch(void* const* d_in, const int* in_sizes, int n_in,
                              void* d_out, int out_size) {
    const float* x   = (const float*)d_in[0];
    const float* wgt = (const float*)d_in[1];
    float* out = (float*)d_out;

    pack_kernel<<<XBLOCKS + OC_, 256>>>(x, wgt);
    dim3 g3(14 * B_, 4);
    xnor_conv_kernel<<<g3, 448>>>(out);
}

// round 15
// speedup vs baseline: 1.7582x; 1.1107x over previous
#include <cuda_runtime.h>
#include <cstdint>

// Problem constants
#define B_   32
#define C_   256
#define H_   58
#define W_   58
#define OC_  256
#define HO_  56
#define WO_  56
#define HW_  (H_*W_)            // 3364
#define NWORDS 8                // 256 channels / 32 bits
#define CN_  2304               // C*KH*KW
#define NINPUT 861184.0f        // C*H*W (alpha normalizer)

// Scratch (device globals; no allocations allowed)
__device__ unsigned g_xpack[B_ * HW_ * NWORDS];        // [b][y][x][w]  3.44 MB
// CSA-form weights: per o, 18 uint4 chunks: chunk=(kh*2+half)*3+cls,
// cls 0 = W0 (kw0), 1 = W1 (kw1), 2 = WX = W0^W1^W2. 73.7 KB, L2-resident.
__device__ uint4    g_wcsa[OC_ * 18];
__device__ float    g_alpha[OC_];

// Forced single-LOP3 3-input ops
template <int LUT>
__device__ __forceinline__ unsigned lop3(unsigned a, unsigned b, unsigned c) {
    unsigned r;
    asm("lop3.b32 %0, %1, %2, %3, %4;" : "=r"(r) : "r"(a), "r"(b), "r"(c), "n"(LUT));
    return r;
}
#define XOR3(a,b,c)  lop3<0x96>(a,b,c)                 // a^b^c
#define MAJ3(a,b,c)  lop3<0xE8>(a,b,c)                 // majority
#define MAJU(x,y,u)  lop3<0xD4>(x,y,u)                 // (x&y)|((x^y)&~u)

// ---------------------------------------------------------------------------
// Fused pack kernel. blocks [0,1792): activations; [1792,2048): weights.
// ---------------------------------------------------------------------------
#define XBLOCKS (B_ * NWORDS * 7)   // 1792

__global__ void __launch_bounds__(256) pack_kernel(const float* __restrict__ x,
                                                   const float* __restrict__ wgt) {
    int blk = blockIdx.x;
    if (blk < XBLOCKS) {
        int b    = blk / 56;
        int rem  = blk % 56;
        int w    = rem / 7;
        int pblk = rem % 7;
        int pos0 = pblk * 512 + threadIdx.x;

        const float* xp = x + ((size_t)(b * C_ + w * 32) * HW_);
        float v0[32], v1[32];
        bool ok0 = pos0 < HW_;
        bool ok1 = pos0 + 256 < HW_;
#pragma unroll
        for (int c = 0; c < 32; c++) {
            size_t off = (size_t)c * HW_;
            v0[c] = ok0 ? __ldg(xp + off + pos0)       : 0.f;
            v1[c] = ok1 ? __ldg(xp + off + pos0 + 256) : 0.f;
        }
        unsigned bits0 = 0, bits1 = 0;
#pragma unroll
        for (int c = 0; c < 32; c++) {
            bits0 |= (v0[c] > 0.5f ? 1u : 0u) << c;
            bits1 |= (v1[c] > 0.5f ? 1u : 0u) << c;
        }
        if (ok0) g_xpack[((size_t)b * HW_ + pos0) * NWORDS + w] = bits0;
        if (ok1) g_xpack[((size_t)b * HW_ + pos0 + 256) * NWORDS + w] = bits1;
    } else {
        // weight packing: ballot bits -> smem, then build g_wcsa + alpha
        int o = blk - XBLOCKS;
        int c = threadIdx.x;
        int lane = c & 31;
        int wrp  = c >> 5;

        __shared__ unsigned sw[72];        // [tap 0..8][word 0..7]
        __shared__ float red[256];

        const float* wp = wgt + (size_t)(o * C_ + c) * 9;
        float asum = 0.f;
#pragma unroll
        for (int k = 0; k < 9; k++) {
            float v = wp[k];
            asum += fabsf(v);
            unsigned word = __ballot_sync(0xffffffffu, v >= 0.f);
            if (lane == 0) sw[k * 8 + wrp] = word;
        }
        red[c] = asum;
        __syncthreads();

        if (c < 72) {
            int chunk = c >> 2, wc = c & 3;
            int kh = chunk / 6, r = chunk % 6;
            int half = r / 3, cls = r % 3;
            int widx = half * 4 + wc;                 // word 0..7
            unsigned val;
            if (cls < 2) val = sw[(kh * 3 + cls) * 8 + widx];
            else         val = sw[(kh * 3 + 0) * 8 + widx]
                             ^ sw[(kh * 3 + 1) * 8 + widx]
                             ^ sw[(kh * 3 + 2) * 8 + widx];
            ((unsigned*)g_wcsa)[o * 72 + chunk * 4 + wc] = val;
        }
#pragma unroll
        for (int s = 128; s > 0; s >>= 1) {
            if (c < s) red[c] += red[c + s];
            __syncthreads();
        }
        if (c == 0) g_alpha[o] = red[0] / NINPUT;
    }
}

// ---------------------------------------------------------------------------
// Conv: thread = (row, x); loop over 64 output channels.
//  - pa/pb pixel columns in REGISTERS (48 regs)
//  - s3 (3-col XOR) precomputed in SMEM (o-independent)
//  - ALL 64 oi weights staged in SMEM once per CTA (18 KB) -> inner loop uses
//    broadcast LDS (2-cyc floor) instead of LDG (4-cyc floor): LSU < alu.
// Two-level CSA math unchanged: u = s3^WX; v = MAJU(pa^W0, pb^W1, u);
// XOR3/MAJ3 over kh; 4 POPC per word, weights (1,2,2,4).
// Block = 224 = 4 rows x 56 x; 2 CTAs/SM (146-reg cap, natural ~110: no spill).
// grid = (14*B_, 4 o-slices).
// ---------------------------------------------------------------------------
__global__ void __launch_bounds__(224, 2)
xnor_conv_kernel(float* __restrict__ out) {
    int bx = blockIdx.x;
    int b  = bx / 14;
    int y0 = (bx % 14) * 4;
    int t  = threadIdx.x;
    int ry = t / 56;
    int xx = t - ry * 56;
    int y  = y0 + ry;
    int o0 = blockIdx.y * 64;

    __shared__ __align__(16) unsigned srow[6 * W_ * NWORDS];   // 11136 B
    __shared__ __align__(16) unsigned s3s[6 * WO_ * NWORDS];   // 10752 B
    __shared__ __align__(16) uint4    sw4[64 * 18];            // 18432 B
    __shared__ float salpha[64];

    // stage 6 contiguous pixel rows (y0 .. y0+5)
    {
        const uint4* src = (const uint4*)(g_xpack + ((size_t)(b * H_ + y0) * W_) * NWORDS);
        const int N4 = 6 * W_ * NWORDS / 4;   // 696
        for (int i = t; i < N4; i += 224) ((uint4*)srow)[i] = src[i];
    }
    // stage weights for this o-slice (64 o x 18 uint4)
    {
        const uint4* wsrc = g_wcsa + (size_t)o0 * 18;
        for (int i = t; i < 64 * 18; i += 224) sw4[i] = __ldg(wsrc + i);
    }
    if (t < 64) salpha[t] = g_alpha[o0 + t];
    __syncthreads();

    // s3s[row][col][w] = srow[row][col] ^ srow[row][col+1] ^ srow[row][col+2]
    for (int i = t; i < 6 * WO_ * NWORDS; i += 224) {
        int row = i / (WO_ * NWORDS);
        int r   = i - row * (WO_ * NWORDS);          // col*8 + w
        int col = r >> 3, w = r & 7;
        int base = (row * W_ + col) * NWORDS + w;
        s3s[i] = XOR3(srow[base], srow[base + NWORDS], srow[base + 2 * NWORDS]);
    }

    // per-thread pixel registers: cols xx (pa), xx+1 (pb); layout [kh*8+half*4+j]
    unsigned pa[24], pb[24];
#pragma unroll
    for (int kh = 0; kh < 3; kh++) {
        int rbase = ((ry + kh) * W_ + xx) * NWORDS;
        uint4 A0 = *(const uint4*)&srow[rbase];
        uint4 A1 = *(const uint4*)&srow[rbase + 4];
        uint4 B0 = *(const uint4*)&srow[rbase + 8];
        uint4 B1 = *(const uint4*)&srow[rbase + 12];
        pa[kh*8+0]=A0.x; pa[kh*8+1]=A0.y; pa[kh*8+2]=A0.z; pa[kh*8+3]=A0.w;
        pa[kh*8+4]=A1.x; pa[kh*8+5]=A1.y; pa[kh*8+6]=A1.z; pa[kh*8+7]=A1.w;
        pb[kh*8+0]=B0.x; pb[kh*8+1]=B0.y; pb[kh*8+2]=B0.z; pb[kh*8+3]=B0.w;
        pb[kh*8+4]=B1.x; pb[kh*8+5]=B1.y; pb[kh*8+6]=B1.z; pb[kh*8+7]=B1.w;
    }
    __syncthreads();

    float* outp = out + (((size_t)b * OC_ + o0) * HO_ + y) * WO_ + xx;

#pragma unroll 2
    for (int oi = 0; oi < 64; oi++) {
        const uint4* wo = &sw4[oi * 18];
        int Su = 0, Cu = 0, Sv = 0, Cv = 0;
#pragma unroll
        for (int half = 0; half < 2; half++) {
            unsigned u[3][4], v[3][4];
#pragma unroll
            for (int kh = 0; kh < 3; kh++) {
                int ch = (kh * 2 + half) * 3;
                uint4 W0 = wo[ch];
                uint4 W1 = wo[ch + 1];
                uint4 WX = wo[ch + 2];
                uint4 s3v = *(const uint4*)&s3s[((ry + kh) * WO_ + xx) * NWORDS + half * 4];
                unsigned Wa[4] = {W0.x, W0.y, W0.z, W0.w};
                unsigned Wb[4] = {W1.x, W1.y, W1.z, W1.w};
                unsigned Wx[4] = {WX.x, WX.y, WX.z, WX.w};
                unsigned sv[4] = {s3v.x, s3v.y, s3v.z, s3v.w};
#pragma unroll
                for (int j = 0; j < 4; j++) {
                    int idx = kh * 8 + half * 4 + j;
                    unsigned uu = sv[j] ^ Wx[j];
                    u[kh][j] = uu;
                    v[kh][j] = MAJU(pa[idx] ^ Wa[j], pb[idx] ^ Wb[j], uu);
                }
            }
#pragma unroll
            for (int j = 0; j < 4; j++) {
                Su += __popc(XOR3(u[0][j], u[1][j], u[2][j]));
                Cu += __popc(MAJ3(u[0][j], u[1][j], u[2][j]));
                Sv += __popc(XOR3(v[0][j], v[1][j], v[2][j]));
                Cv += __popc(MAJ3(v[0][j], v[1][j], v[2][j]));
            }
        }
        int P = Su + ((Cu + Sv) << 1) + (Cv << 2);
        float a = salpha[oi];
        *outp = fmaf(-2.0f * a, (float)P, a * (float)CN_);
        outp += (size_t)HO_ * WO_;
    }
}

// ---------------------------------------------------------------------------
extern "C" void kernel_launch(void* const* d_in, const int* in_sizes, int n_in,
                              void* d_out, int out_size) {
    const float* x   = (const float*)d_in[0];
    const float* wgt = (const float*)d_in[1];
    float* out = (float*)d_out;

    pack_kernel<<<XBLOCKS + OC_, 256>>>(x, wgt);
    dim3 g3(14 * B_, 4);
    xnor_conv_kernel<<<g3, 224>>>(out);
}

// round 16
// speedup vs baseline: 1.9227x; 1.0935x over previous
#include <cuda_runtime.h>
#include <cstdint>

// Problem constants
#define B_   32
#define C_   256
#define H_   58
#define W_   58
#define OC_  256
#define KH_  3
#define KW_  3
#define HO_  56
#define WO_  56
#define HW_  (H_*W_)            // 3364
#define NWORDS 8                // 256 channels / 32 bits
#define CN_  2304               // C*KH*KW
#define NINPUT 861184.0f        // C*H*W (alpha normalizer)

// Scratch (device globals; no allocations allowed)
__device__ unsigned g_xpack[B_ * HW_ * NWORDS];        // [b][y][x][w]  3.44 MB
__device__ unsigned g_wpack[OC_ * KH_ * KW_ * NWORDS]; // [o][k][w]     73.7 KB
__device__ float    g_alpha[OC_];

// Forced single-LOP3 3-input ops
template <int LUT>
__device__ __forceinline__ unsigned lop3(unsigned a, unsigned b, unsigned c) {
    unsigned r;
    asm("lop3.b32 %0, %1, %2, %3, %4;" : "=r"(r) : "r"(a), "r"(b), "r"(c), "n"(LUT));
    return r;
}
#define XOR3(a,b,c)  lop3<0x96>(a,b,c)                 // a^b^c
#define MAJ3(a,b,c)  lop3<0xE8>(a,b,c)                 // majority
#define MAJU(x,y,u)  lop3<0xD4>(x,y,u)                 // (x&y)|((x^y)&~u)

// ---------------------------------------------------------------------------
// Fused pack kernel.
//   blocks [0,1024): activations — 4 consecutive positions per thread via
//   32 independent LDG.128 (high MLP, 1 load-inst per 16B).
//   blocks [1024,1280): weights (ballot) + alpha.
// HW_ = 3364 = 4*841 exactly; float4 alignment holds (3364 % 4 == 0).
// ---------------------------------------------------------------------------
#define XBLOCKS (B_ * NWORDS * 4)   // 1024

__global__ void __launch_bounds__(256) pack_kernel(const float* __restrict__ x,
                                                   const float* __restrict__ wgt) {
    int blk = blockIdx.x;
    if (blk < XBLOCKS) {
        int b    = blk >> 5;            // / 32
        int rem  = blk & 31;
        int w    = rem >> 2;            // / 4
        int gblk = rem & 3;
        int g    = gblk * 256 + threadIdx.x;      // float4 group index
        if (g >= HW_ / 4) return;                 // 841 groups

        const float4* xp = (const float4*)(x + ((size_t)(b * C_ + w * 32) * HW_));
        unsigned b0 = 0, b1 = 0, b2 = 0, b3 = 0;
#pragma unroll
        for (int c = 0; c < 32; c++) {
            float4 v = __ldg(xp + (size_t)c * (HW_ / 4) + g);
            b0 |= (v.x > 0.5f ? 1u : 0u) << c;
            b1 |= (v.y > 0.5f ? 1u : 0u) << c;
            b2 |= (v.z > 0.5f ? 1u : 0u) << c;
            b3 |= (v.w > 0.5f ? 1u : 0u) << c;
        }
        size_t base = ((size_t)b * HW_ + 4 * g) * NWORDS + w;
        g_xpack[base]              = b0;
        g_xpack[base + NWORDS]     = b1;
        g_xpack[base + 2 * NWORDS] = b2;
        g_xpack[base + 3 * NWORDS] = b3;
    } else {
        int o = blk - XBLOCKS;
        int c = threadIdx.x;
        int lane = c & 31;
        int wrp  = c >> 5;

        const float* wp = wgt + (size_t)(o * C_ + c) * (KH_ * KW_);
        float asum = 0.f;
#pragma unroll
        for (int k = 0; k < KH_ * KW_; k++) {
            float v = wp[k];
            asum += fabsf(v);
            unsigned word = __ballot_sync(0xffffffffu, v >= 0.f);
            if (lane == 0) g_wpack[(o * 9 + k) * NWORDS + wrp] = word;
        }

        __shared__ float red[256];
        red[c] = asum;
        __syncthreads();
#pragma unroll
        for (int s = 128; s > 0; s >>= 1) {
            if (c < s) red[c] += red[c + s];
            __syncthreads();
        }
        if (c == 0) g_alpha[o] = red[0] / NINPUT;
    }
}

// ---------------------------------------------------------------------------
// Conv (R10, the measured optimum): two-level CSA XNOR conv, 3 CTAs/SM,
// fma-pipe epilogue, x0 loop unrolled 2x.
// grid = (B_*HO_, 2), block = 128 (thread = output channel within half).
// ---------------------------------------------------------------------------
__global__ void __launch_bounds__(128, 3)
xnor_conv_kernel(float* __restrict__ out) {
    int by = blockIdx.x;
    int b  = by / HO_;
    int y  = by % HO_;
    int o  = blockIdx.y * 128 + threadIdx.x;
    int t  = threadIdx.x;

    __shared__ __align__(16) unsigned sx[3 * W_  * NWORDS];  // 5568 B
    __shared__ __align__(16) unsigned s3[3 * WO_ * NWORDS];  // 5376 B

    // load 3 packed rows
    const int ROW4 = W_ * NWORDS / 4; // 116 uint4 per row
    for (int i = t; i < 3 * ROW4; i += 128) {
        int kh = i / ROW4;
        int r  = i - kh * ROW4;
        const uint4* src = (const uint4*)(g_xpack + ((size_t)(b * H_ + y + kh) * W_) * NWORDS);
        ((uint4*)sx)[kh * ROW4 + r] = src[r];
    }

    // per-thread weights: w0, w1 (kw taps 0,1) and wx3 = w0^w1^w2, [kh*8+w]
    unsigned w0[24], w1[24], wx3[24];
    {
        const uint4* wp4 = (const uint4*)(g_wpack + (size_t)o * 72);
#pragma unroll
        for (int kh = 0; kh < 3; kh++) {
            uint4 a0 = wp4[(kh * 3 + 0) * 2], a1 = wp4[(kh * 3 + 0) * 2 + 1];
            uint4 b0 = wp4[(kh * 3 + 1) * 2], b1 = wp4[(kh * 3 + 1) * 2 + 1];
            uint4 c0 = wp4[(kh * 3 + 2) * 2], c1 = wp4[(kh * 3 + 2) * 2 + 1];
            ((uint4*)w0)[kh * 2] = a0; ((uint4*)w0)[kh * 2 + 1] = a1;
            ((uint4*)w1)[kh * 2] = b0; ((uint4*)w1)[kh * 2 + 1] = b1;
            wx3[kh * 8 + 0] = a0.x ^ b0.x ^ c0.x;
            wx3[kh * 8 + 1] = a0.y ^ b0.y ^ c0.y;
            wx3[kh * 8 + 2] = a0.z ^ b0.z ^ c0.z;
            wx3[kh * 8 + 3] = a0.w ^ b0.w ^ c0.w;
            wx3[kh * 8 + 4] = a1.x ^ b1.x ^ c1.x;
            wx3[kh * 8 + 5] = a1.y ^ b1.y ^ c1.y;
            wx3[kh * 8 + 6] = a1.z ^ b1.z ^ c1.z;
            wx3[kh * 8 + 7] = a1.w ^ b1.w ^ c1.w;
        }
    }
    float a = g_alpha[o];
    float base = a * (float)CN_;     // out = base + na * P
    float na   = -2.0f * a;
    __syncthreads();

    // s3[kh][c][w] = sx[kh][c] ^ sx[kh][c+1] ^ sx[kh][c+2]
    for (int i = t; i < 3 * WO_ * NWORDS; i += 128) {
        int kh = i / (WO_ * NWORDS);
        int r  = i - kh * (WO_ * NWORDS);
        int bidx = kh * (W_ * NWORDS) + r;
        s3[i] = XOR3(sx[bidx], sx[bidx + NWORDS], sx[bidx + 2 * NWORDS]);
    }
    __syncthreads();

    float* outp = out + ((size_t)(b * OC_ + o) * HO_ + y) * WO_;

#pragma unroll 2
    for (int x0 = 0; x0 < WO_; x0 += 2) {
        int Su0 = 0, Cu0 = 0, Sv0 = 0, Cv0 = 0;
        int Su1 = 0, Cu1 = 0, Sv1 = 0, Cv1 = 0;
#pragma unroll
        for (int half = 0; half < 2; half++) {
            unsigned u[3][2][4], v[3][2][4];     // [kh][xi][j]
#pragma unroll
            for (int kh = 0; kh < 3; kh++) {
                const unsigned* rp = &sx[(kh * W_ + x0) * NWORDS + half * 4];
                uint4 q0 = *(const uint4*)(rp);
                uint4 q1 = *(const uint4*)(rp + NWORDS);
                uint4 q2 = *(const uint4*)(rp + 2 * NWORDS);
                const unsigned* rs = &s3[(kh * WO_ + x0) * NWORDS + half * 4];
                uint4 t0 = *(const uint4*)(rs);
                uint4 t1 = *(const uint4*)(rs + NWORDS);
                unsigned p0[4] = {q0.x, q0.y, q0.z, q0.w};
                unsigned p1[4] = {q1.x, q1.y, q1.z, q1.w};
                unsigned p2[4] = {q2.x, q2.y, q2.z, q2.w};
                unsigned s0[4] = {t0.x, t0.y, t0.z, t0.w};
                unsigned s1[4] = {t1.x, t1.y, t1.z, t1.w};
#pragma unroll
                for (int j = 0; j < 4; j++) {
                    int wi = kh * 8 + half * 4 + j;
                    unsigned W0 = w0[wi], W1 = w1[wi], WX = wx3[wi];
                    unsigned u0 = s0[j] ^ WX;
                    unsigned u1 = s1[j] ^ WX;
                    u[kh][0][j] = u0;
                    u[kh][1][j] = u1;
                    v[kh][0][j] = MAJU(p0[j] ^ W0, p1[j] ^ W1, u0);
                    v[kh][1][j] = MAJU(p1[j] ^ W0, p2[j] ^ W1, u1);
                }
            }
#pragma unroll
            for (int j = 0; j < 4; j++) {
                Su0 += __popc(XOR3(u[0][0][j], u[1][0][j], u[2][0][j]));
                Cu0 += __popc(MAJ3(u[0][0][j], u[1][0][j], u[2][0][j]));
                Sv0 += __popc(XOR3(v[0][0][j], v[1][0][j], v[2][0][j]));
                Cv0 += __popc(MAJ3(v[0][0][j], v[1][0][j], v[2][0][j]));
                Su1 += __popc(XOR3(u[0][1][j], u[1][1][j], u[2][1][j]));
                Cu1 += __popc(MAJ3(u[0][1][j], u[1][1][j], u[2][1][j]));
                Sv1 += __popc(XOR3(v[0][1][j], v[1][1][j], v[2][1][j]));
                Cv1 += __popc(MAJ3(v[0][1][j], v[1][1][j], v[2][1][j]));
            }
        }
        int P0 = Su0 + ((Cu0 + Sv0) << 1) + (Cv0 << 2);
        int P1 = Su1 + ((Cu1 + Sv1) << 1) + (Cv1 << 2);
        float2 r;
        r.x = fmaf(na, (float)P0, base);
        r.y = fmaf(na, (float)P1, base);
        *(float2*)(outp + x0) = r;
    }
}

// ---------------------------------------------------------------------------
extern "C" void kernel_launch(void* const* d_in, const int* in_sizes, int n_in,
                              void* d_out, int out_size) {
    const float* x   = (const float*)d_in[0];
    const float* wgt = (const float*)d_in[1];
    float* out = (float*)d_out;

    pack_kernel<<<XBLOCKS + OC_, 256>>>(x, wgt);
    dim3 g3(B_ * HO_, 2);
    xnor_conv_kernel<<<g3, 128>>>(out);
}